// round 9
// baseline (speedup 1.0000x reference)
#include <cuda_runtime.h>
#include <math.h>
#include <stdint.h>

#define NSRC   2048
#define NGRID  50000
#define NLOCS  500
#define KTOP   5
#define NSLICE 256
#define SL     196          // ceil(50000/256); last slice has 20 points
#define NPAIR  98           // SL/2
#define SPT    4            // sources per thread in slice_min
#define SMT    128          // threads in slice_min
#define FINF   __int_as_float(0x7f800000)
#define IBIG   0x7fffffff

// ---------------- device scratch ----------------
__device__ float g_sd[NSRC * NSLICE];      // per (src, slice) min "e"

// ---------------- f32x2 packed helpers (sm_103a FFMA2) ----------------
__device__ __forceinline__ unsigned long long pk2(float lo, float hi) {
    unsigned long long r;
    asm("mov.b64 %0, {%1, %2};"
        : "=l"(r) : "r"(__float_as_uint(lo)), "r"(__float_as_uint(hi)));
    return r;
}
__device__ __forceinline__ unsigned long long fma2(unsigned long long a,
                                                   unsigned long long b,
                                                   unsigned long long c) {
    unsigned long long d;
    asm("fma.rn.f32x2 %0, %1, %2, %3;" : "=l"(d) : "l"(a), "l"(b), "l"(c));
    return d;
}
__device__ __forceinline__ void upk2(unsigned long long v, float& lo, float& hi) {
    unsigned int a, b;
    asm("mov.b64 {%0, %1}, %2;" : "=r"(a), "=r"(b) : "l"(v));
    lo = __uint_as_float(a);
    hi = __uint_as_float(b);
}
__device__ __forceinline__ float fsqrt_approx(float x) {
    float r;
    asm("sqrt.approx.f32 %0, %1;" : "=f"(r) : "f"(x));
    return r;
}

// lexicographic (value, index): lower value wins; tie -> lower index
__device__ __forceinline__ bool lexless(float a, int ai, float b, int bi) {
    return (a < b) || (a == b && ai < bi);
}

// ============ kernel 1: per-(src, slice) branchless minimum ============
// grid = (4, 256); 128 threads; SPT=4 sources per thread.
// Compile-time 98-pair loop (last slice padded to +inf e).
// Ordering key: e = |g|^2 - 2*s.g  (== d2 - |s|^2, same order as ref d2).
__global__ __launch_bounds__(SMT)
void slice_min_kernel(const float* __restrict__ src,
                      const float* __restrict__ grid) {
    __shared__ float4 tileA[NPAIR];   // (x0, x1, y0, y1)
    __shared__ float4 tileB[NPAIR];   // (z0, z1, w0, w1)

    const int slice = blockIdx.y;
    const int base  = slice * SL;
    const int n     = min(SL, NGRID - base);      // 196 or 20

    if (threadIdx.x < NPAIR) {
        const int p  = threadIdx.x;
        const int j0 = 2 * p;
        const int j1 = j0 + 1;
        // pad coords 1e30 -> w = inf -> e = finite + inf = +inf (no NaN)
        float x0 = 1e30f, y0 = 1e30f, z0 = 1e30f, w0;
        float x1 = 1e30f, y1 = 1e30f, z1 = 1e30f, w1;
        if (j0 < n) {
            const int g0 = base + j0;
            x0 = grid[g0 * 3 + 0] / 1000.0f;
            y0 = grid[g0 * 3 + 1] / 1000.0f;
            z0 = grid[g0 * 3 + 2] / 1000.0f;
        }
        if (j1 < n) {
            const int g1 = base + j1;
            x1 = grid[g1 * 3 + 0] / 1000.0f;
            y1 = grid[g1 * 3 + 1] / 1000.0f;
            z1 = grid[g1 * 3 + 2] / 1000.0f;
        }
        w0 = __fadd_rn(__fadd_rn(__fmul_rn(x0, x0), __fmul_rn(y0, y0)),
                       __fmul_rn(z0, z0));
        w1 = __fadd_rn(__fadd_rn(__fmul_rn(x1, x1), __fmul_rn(y1, y1)),
                       __fmul_rn(z1, z1));
        tileA[p] = make_float4(x0, x1, y0, y1);
        tileB[p] = make_float4(z0, z1, w0, w1);
    }
    __syncthreads();

    const int s0 = blockIdx.x * (SMT * SPT) + threadIdx.x;

    unsigned long long mx2[SPT], my2[SPT], mz2[SPT];
#pragma unroll
    for (int k = 0; k < SPT; k++) {
        const int s = s0 + k * SMT;
        float mx = -2.0f * (src[s * 3 + 0] / 1000.0f);
        float my = -2.0f * (src[s * 3 + 1] / 1000.0f);
        float mz = -2.0f * (src[s * 3 + 2] / 1000.0f);
        mx2[k] = pk2(mx, mx);
        my2[k] = pk2(my, my);
        mz2[k] = pk2(mz, mz);
    }

    float accL[SPT], accH[SPT];
#pragma unroll
    for (int k = 0; k < SPT; k++) { accL[k] = FINF; accH[k] = FINF; }

#pragma unroll 7
    for (int p = 0; p < NPAIR; p++) {
        float4 A = tileA[p];
        float4 B = tileB[p];
        unsigned long long xx = pk2(A.x, A.y);
        unsigned long long yy = pk2(A.z, A.w);
        unsigned long long zz = pk2(B.x, B.y);
        unsigned long long ww = pk2(B.z, B.w);
#pragma unroll
        for (int k = 0; k < SPT; k++) {
            unsigned long long e = fma2(mz2[k], zz, ww);
            e = fma2(my2[k], yy, e);
            e = fma2(mx2[k], xx, e);
            float lo, hi;
            upk2(e, lo, hi);
            accL[k] = fminf(accL[k], lo);
            accH[k] = fminf(accH[k], hi);
        }
    }

#pragma unroll
    for (int k = 0; k < SPT; k++) {
        const int s = s0 + k * SMT;
        g_sd[s * NSLICE + slice] = fminf(accL[k], accH[k]);
    }
}

// ============ kernel 2: fused select + bias mean + epilogue ============
// 512 blocks x 512 threads; block handles 4 sources.
//  phase 1 (warps 0-3, one source each, warp-sync only):
//     A) per-lane bubble top-5 of its 8 slice minima, 5 warp-merge rounds
//        -> 5 candidate slices (contain the global top-5; lex tie-break).
//     B) rescan <=980 candidate points (IEEE-identical e), per-lane
//        bubble top-5 by (e, gidx), 5 warp-merge rounds -> tk[4][5].
//  phase 2 (all): bias means (coalesced row streams) -> bsum[4][500].
//  phase 3 (all): epilogue, 4 outputs per thread.
__global__ __launch_bounds__(512)
void tail_kernel(const float* __restrict__ src,
                 const int*   __restrict__ ind,
                 const float* __restrict__ log_amp,
                 const int*   __restrict__ phase,
                 const float* __restrict__ locs,
                 const float* __restrict__ mag_coef,
                 const float* __restrict__ eps_coef,
                 const float* __restrict__ dep_coef,
                 const float* __restrict__ bias,
                 const float* __restrict__ grid,
                 float*       __restrict__ out) {
    const int s0   = blockIdx.x * 4;
    const int tid  = threadIdx.x;
    const int wid  = tid >> 5;
    const int lane = tid & 31;

    __shared__ int   tks[4 * KTOP];
    __shared__ float bsum[4][NLOCS];

    if (wid < 4) {
        const int s = s0 + wid;

        // ---- stage A: top-5 slice minima over 256 slices ----
        float t0 = FINF, t1 = FINF, t2 = FINF, t3 = FINF, t4 = FINF;
        int   i0 = IBIG, i1 = IBIG, i2 = IBIG, i3 = IBIG, i4 = IBIG;
#pragma unroll
        for (int i = 0; i < 8; i++) {
            const int sid = lane + 32 * i;
            const float v = g_sd[s * NSLICE + sid];
            if (lexless(v, sid, t4, i4)) {
                t4 = v; i4 = sid;
                if (lexless(t4, i4, t3, i3)) {
                    float tv = t3; t3 = t4; t4 = tv;
                    int   ti = i3; i3 = i4; i4 = ti;
                    if (lexless(t3, i3, t2, i2)) {
                        tv = t2; t2 = t3; t3 = tv;
                        ti = i2; i2 = i3; i3 = ti;
                        if (lexless(t2, i2, t1, i1)) {
                            tv = t1; t1 = t2; t2 = tv;
                            ti = i1; i1 = i2; i2 = ti;
                            if (lexless(t1, i1, t0, i0)) {
                                tv = t0; t0 = t1; t1 = tv;
                                ti = i0; i0 = i1; i1 = ti;
                            }
                        }
                    }
                }
            }
        }
        int cs[KTOP];
#pragma unroll
        for (int r = 0; r < KTOP; r++) {
            float bv = t0; int bi = i0;
#pragma unroll
            for (int off = 16; off > 0; off >>= 1) {
                float ov = __shfl_xor_sync(0xffffffffu, bv, off);
                int   oi = __shfl_xor_sync(0xffffffffu, bi, off);
                if (lexless(ov, oi, bv, bi)) { bv = ov; bi = oi; }
            }
            cs[r] = bi;
            if (t0 == bv && i0 == bi) {        // slice ids unique
                t0 = t1; i0 = i1; t1 = t2; i1 = i2;
                t2 = t3; i2 = i3; t3 = t4; i3 = i4;
                t4 = FINF; i4 = IBIG;
            }
        }

        // ---- stage B: rescan candidate slices, per-lane top-5 ----
        const float mx = -2.0f * (src[s * 3 + 0] / 1000.0f);
        const float my = -2.0f * (src[s * 3 + 1] / 1000.0f);
        const float mz = -2.0f * (src[s * 3 + 2] / 1000.0f);

        t0 = FINF; t1 = FINF; t2 = FINF; t3 = FINF; t4 = FINF;
        i0 = IBIG; i1 = IBIG; i2 = IBIG; i3 = IBIG; i4 = IBIG;

#pragma unroll
        for (int r = 0; r < KTOP; r++) {
            const int sb = cs[r] * SL;
#pragma unroll
            for (int i = 0; i < 7; i++) {
                const int j = lane + 32 * i;
                if (j >= SL) break;
                const int gi = sb + j;
                if (gi >= NGRID) continue;
                const float x = grid[gi * 3 + 0] / 1000.0f;
                const float y = grid[gi * 3 + 1] / 1000.0f;
                const float z = grid[gi * 3 + 2] / 1000.0f;
                const float n2 = __fadd_rn(__fadd_rn(__fmul_rn(x, x),
                                                     __fmul_rn(y, y)),
                                           __fmul_rn(z, z));
                const float e = fmaf(mx, x, fmaf(my, y, fmaf(mz, z, n2)));
                if (lexless(e, gi, t4, i4)) {
                    t4 = e; i4 = gi;
                    if (lexless(t4, i4, t3, i3)) {
                        float tv = t3; t3 = t4; t4 = tv;
                        int   ti = i3; i3 = i4; i4 = ti;
                        if (lexless(t3, i3, t2, i2)) {
                            tv = t2; t2 = t3; t3 = tv;
                            ti = i2; i2 = i3; i3 = ti;
                            if (lexless(t2, i2, t1, i1)) {
                                tv = t1; t1 = t2; t2 = tv;
                                ti = i1; i1 = i2; i2 = ti;
                                if (lexless(t1, i1, t0, i0)) {
                                    tv = t0; t0 = t1; t1 = tv;
                                    ti = i0; i0 = i1; i1 = ti;
                                }
                            }
                        }
                    }
                }
            }
        }

#pragma unroll
        for (int r = 0; r < KTOP; r++) {
            float bv = t0; int bi = i0;
#pragma unroll
            for (int off = 16; off > 0; off >>= 1) {
                float ov = __shfl_xor_sync(0xffffffffu, bv, off);
                int   oi = __shfl_xor_sync(0xffffffffu, bi, off);
                if (lexless(ov, oi, bv, bi)) { bv = ov; bi = oi; }
            }
            if (lane == 0) tks[wid * KTOP + r] = bi;
            if (t0 == bv && i0 == bi) {        // grid ids unique
                t0 = t1; i0 = i1; t1 = t2; i1 = i2;
                t2 = t3; i2 = i3; t3 = t4; i3 = i4;
                t4 = FINF; i4 = IBIG;
            }
        }
    }
    __syncthreads();

    const int ph = phase[0];

    // ---- phase 2: bias means for 4 sources ----
    for (int task = tid; task < 4 * NLOCS; task += 512) {
        const int ss = task / NLOCS;
        const int j  = task - ss * NLOCS;
        const int col = j * 2 + ph;
        float acc = __ldg(&bias[(size_t)tks[ss * KTOP + 0] * (NLOCS * 2) + col]);
        acc += __ldg(&bias[(size_t)tks[ss * KTOP + 1] * (NLOCS * 2) + col]);
        acc += __ldg(&bias[(size_t)tks[ss * KTOP + 2] * (NLOCS * 2) + col]);
        acc += __ldg(&bias[(size_t)tks[ss * KTOP + 3] * (NLOCS * 2) + col]);
        acc += __ldg(&bias[(size_t)tks[ss * KTOP + 4] * (NLOCS * 2) + col]);
        bsum[ss][j] = acc / 5.0f;
    }
    __syncthreads();

    // ---- phase 3: epilogue, 4 outputs per thread ----
    if (tid >= NLOCS) return;

    const float ec    = eps_coef[ph];
    const float dc    = dep_coef[ph];
    const float denom = fmaxf(mag_coef[ph], 1e-12f);

    const int li = ind[tid];
    const float lx = locs[li * 3 + 0];
    const float ly = locs[li * 3 + 1];
    const float lz = locs[li * 3 + 2];

#pragma unroll
    for (int ss = 0; ss < 4; ss++) {
        const int s = s0 + ss;
        const float sx = src[s * 3 + 0];
        const float sy = src[s * 3 + 1];
        const float sz = src[s * 3 + 2];

        const float dx = sx - lx;
        const float dy = sy - ly;
        const float d0  = fsqrt_approx(__fadd_rn(__fmul_rn(dx, dx),
                                                 __fmul_rn(dy, dy)));
        const float ld0 = __log10f(d0 + 1.0f);
        const float ldd = __log10f(fabsf(sz - lz) + 1.0f);

        const float b  = bsum[ss][li];
        const float la = log_amp[s * NLOCS + tid];
        out[s * NLOCS + tid] = (la - ec * ld0 - dc * ldd - b) / denom;
    }
}

// ---------------- launch ----------------
extern "C" void kernel_launch(void* const* d_in, const int* in_sizes, int n_in,
                              void* d_out, int out_size) {
    const float* src      = (const float*)d_in[0];
    const int*   ind      = (const int*)  d_in[1];
    const float* log_amp  = (const float*)d_in[2];
    const int*   phase    = (const int*)  d_in[3];
    const float* locs     = (const float*)d_in[4];
    const float* grid     = (const float*)d_in[5];
    const float* mag_coef = (const float*)d_in[6];
    const float* eps_coef = (const float*)d_in[7];
    const float* dep_coef = (const float*)d_in[8];
    const float* bias     = (const float*)d_in[9];
    float* out = (float*)d_out;

    dim3 g1(NSRC / (SMT * SPT), NSLICE);
    slice_min_kernel<<<g1, SMT>>>(src, grid);

    tail_kernel<<<NSRC / 4, 512>>>(src, ind, log_amp, phase, locs,
                                   mag_coef, eps_coef, dep_coef, bias,
                                   grid, out);
}